// round 7
// baseline (speedup 1.0000x reference)
#include <cuda_runtime.h>
#include <cuda_bf16.h>
#include <cstdint>

typedef unsigned int u32;

#define BB 4
#define TT 2048
#define DDIM 512
#define HH 8
#define DKH 64

#define SZQ ((size_t)BB * HH * TT * DKH)   // 4,194,304
#define SZX ((size_t)BB * TT * DDIM)       // 4,194,304
#define SZW ((size_t)DDIM * DDIM)          // 262,144

// ---------------- scratch (__device__ globals; no allocation) ----------------
__device__ __nv_bfloat16 g_xh[3][SZX], g_xl[3][SZX];     // query/key/value inputs
__device__ __nv_bfloat16 g_wh[4][SZW],  g_wl[4][SZW];    // Wq, Wk, Wv, Wo
__device__ __nv_bfloat16 g_qh[SZQ], g_ql[SZQ];           // [B,H,T,DK]
__device__ __nv_bfloat16 g_kh[SZQ], g_kl[SZQ];           // [B,H,T,DK]
__device__ __nv_bfloat16 g_vth[SZQ], g_vtl[SZQ];         // [B,H,DK,T]
__device__ __nv_bfloat16 g_ch[SZX], g_cl[SZX];           // ctx [B,T,D] (normalized)
__device__ u32 g_mbits[(size_t)BB * TT * (TT / 32)];     // packed mask bits

// ---------------- helpers ----------------
__device__ __forceinline__ u32 smem_u32(const void* p) {
    u32 a;
    asm("{ .reg .u64 t; cvta.to.shared.u64 t, %1; cvt.u32.u64 %0, t; }" : "=r"(a) : "l"(p));
    return a;
}
__device__ __forceinline__ void split_hl(float v, __nv_bfloat16& h, __nv_bfloat16& l) {
    h = __float2bfloat16(v);
    l = __float2bfloat16(v - __bfloat162float(h));
}
__device__ __forceinline__ u32 pack2(__nv_bfloat16 a, __nv_bfloat16 b) {
    return (u32)__bfloat16_as_ushort(a) | ((u32)__bfloat16_as_ushort(b) << 16);
}
__device__ __forceinline__ void ldsm_x4(u32& r0, u32& r1, u32& r2, u32& r3, u32 addr) {
    asm volatile("ldmatrix.sync.aligned.m8n8.x4.shared.b16 {%0,%1,%2,%3}, [%4];"
                 : "=r"(r0), "=r"(r1), "=r"(r2), "=r"(r3) : "r"(addr));
}
__device__ __forceinline__ void mma16816(float* c, const u32* a, u32 b0, u32 b1) {
    asm volatile(
        "mma.sync.aligned.m16n8k16.row.col.f32.bf16.bf16.f32 "
        "{%0,%1,%2,%3}, {%4,%5,%6,%7}, {%8,%9}, {%0,%1,%2,%3};"
        : "+f"(c[0]), "+f"(c[1]), "+f"(c[2]), "+f"(c[3])
        : "r"(a[0]), "r"(a[1]), "r"(a[2]), "r"(a[3]), "r"(b0), "r"(b1));
}

#define CP_COMMIT() asm volatile("cp.async.commit_group;" ::: "memory")
#define CP_WAIT(n)  asm volatile("cp.async.wait_group %0;" :: "n"(n) : "memory")

// Copy ROWS x KW bf16 tile (K-major, 16B chunks) into smem with +8 elem pad.
template <int ROWS, int KW>
__device__ __forceinline__ void cp_tile(u32 sbase, const __nv_bfloat16* __restrict__ g,
                                        size_t ld, size_t row0, size_t k0, int tid)
{
    constexpr int PR = KW / 8;
    constexpr int CH = ROWS * PR;
    #pragma unroll
    for (int i = tid; i < CH; i += 256) {
        int r = i / PR, c = i % PR;
        u32 dst = sbase + (u32)((r * (KW + 8) + c * 8) * 2);
        const void* src = g + (row0 + (size_t)r) * ld + k0 + c * 8;
        asm volatile("cp.async.cg.shared.global [%0], [%1], 16;" :: "r"(dst), "l"(src));
    }
}

// warp-MMA over one 32-wide K slab, bf16x3 emulation (3 MMA terms)
template <int MF, int NF, int AS, int BS>
__device__ __forceinline__ void mma_hl(
    const __nv_bfloat16 (*Ah)[AS], const __nv_bfloat16 (*Al)[AS],
    const __nv_bfloat16 (*Bh)[BS], const __nv_bfloat16 (*Bl)[BS],
    int wrow, int wcol, int lane, int kA, int kB, float acc[MF][NF][4])
{
    const int arow = wrow + (lane & 15);
    const int akh = (lane >> 4) << 3;
    const int brow = wcol + (lane & 7) + ((lane & 16) >> 1);
    const int bkh = (lane & 8);
    #pragma unroll
    for (int ks = 0; ks < 32; ks += 16) {
        u32 ah[MF][4], al[MF][4];
        #pragma unroll
        for (int mf = 0; mf < MF; mf++) {
            ldsm_x4(ah[mf][0], ah[mf][1], ah[mf][2], ah[mf][3],
                    smem_u32(&Ah[arow + mf * 16][kA + ks + akh]));
            ldsm_x4(al[mf][0], al[mf][1], al[mf][2], al[mf][3],
                    smem_u32(&Al[arow + mf * 16][kA + ks + akh]));
        }
        #pragma unroll
        for (int np = 0; np < NF / 2; np++) {
            u32 bh0, bh1, bh2, bh3, bl0, bl1, bl2, bl3;
            ldsm_x4(bh0, bh1, bh2, bh3, smem_u32(&Bh[brow + np * 16][kB + ks + bkh]));
            ldsm_x4(bl0, bl1, bl2, bl3, smem_u32(&Bl[brow + np * 16][kB + ks + bkh]));
            #pragma unroll
            for (int mf = 0; mf < MF; mf++) {
                mma16816(acc[mf][2 * np],     ah[mf], bh0, bh1);
                mma16816(acc[mf][2 * np],     ah[mf], bl0, bl1);
                mma16816(acc[mf][2 * np],     al[mf], bh0, bh1);
                mma16816(acc[mf][2 * np + 1], ah[mf], bh2, bh3);
                mma16816(acc[mf][2 * np + 1], ah[mf], bl2, bl3);
                mma16816(acc[mf][2 * np + 1], al[mf], bh2, bh3);
            }
        }
    }
}

// ---------------- conversion kernels (write device globals via selector) -----
__global__ __launch_bounds__(256) void cvt_x(const float4* __restrict__ in, int slot)
{
    size_t i = (size_t)blockIdx.x * 256 + threadIdx.x;
    float4 v = in[i];
    __nv_bfloat16 h0, l0, h1, l1, h2, l2, h3, l3;
    split_hl(v.x, h0, l0); split_hl(v.y, h1, l1);
    split_hl(v.z, h2, l2); split_hl(v.w, h3, l3);
    ((uint2*)g_xh[slot])[i] = make_uint2(pack2(h0, h1), pack2(h2, h3));
    ((uint2*)g_xl[slot])[i] = make_uint2(pack2(l0, l1), pack2(l2, l3));
}
__global__ __launch_bounds__(256) void cvt_w(const float4* __restrict__ in, int slot)
{
    size_t i = (size_t)blockIdx.x * 256 + threadIdx.x;
    float4 v = in[i];
    __nv_bfloat16 h0, l0, h1, l1, h2, l2, h3, l3;
    split_hl(v.x, h0, l0); split_hl(v.y, h1, l1);
    split_hl(v.z, h2, l2); split_hl(v.w, h3, l3);
    ((uint2*)g_wh[slot])[i] = make_uint2(pack2(h0, h1), pack2(h2, h3));
    ((uint2*)g_wl[slot])[i] = make_uint2(pack2(l0, l1), pack2(l2, l3));
}
__global__ __launch_bounds__(256) void cvt_mask_kernel(const int* __restrict__ mask)
{
    size_t i = (size_t)blockIdx.x * 256 + threadIdx.x;
    u32 bit = (mask[i] != 0) ? 1u : 0u;
    u32 word = __ballot_sync(0xffffffffu, bit);
    if ((threadIdx.x & 31) == 0) g_mbits[i >> 5] = word;
}

// ---------------- gemm512: C = A @ B^T + bias (M=8192, N=512, K=512) ---------
// asel: 0..2 -> g_x[asel]; 3 -> g_c (ctx).  wsel selects g_w.
// dst 0 -> g_q hi/lo; 1 -> g_k; 2 -> g_vt [B,H,DK,T]; 3 -> fp32 outf
// dynamic smem: 2 stages x {Ah,Al,Bh,Bl} 128x40 bf16 = 81,920 B
__global__ __launch_bounds__(256, 2) void gemm512(int asel, int wsel,
                                                  const float* __restrict__ bias,
                                                  int dst, float* __restrict__ outf)
{
    extern __shared__ char dyn[];
    const int tid = threadIdx.x, lane = tid & 31, wid = tid >> 5;
    const int wrow = (wid >> 1) * 32, wcol = (wid & 1) * 64;
    const int tile_m = blockIdx.y * 128, tile_n = blockIdx.x * 128;
    const u32 sb = smem_u32(dyn);

    const __nv_bfloat16* Ah_g = (asel < 3) ? g_xh[asel] : g_ch;
    const __nv_bfloat16* Al_g = (asel < 3) ? g_xl[asel] : g_cl;
    const __nv_bfloat16* Bh_g = g_wh[wsel];
    const __nv_bfloat16* Bl_g = g_wl[wsel];

    auto issue = [&](int s, int k0) {
        u32 base = sb + s * 40960;
        cp_tile<128, 32>(base,         Ah_g, DDIM, tile_m, k0, tid);
        cp_tile<128, 32>(base + 10240, Al_g, DDIM, tile_m, k0, tid);
        cp_tile<128, 32>(base + 20480, Bh_g, DDIM, tile_n, k0, tid);
        cp_tile<128, 32>(base + 30720, Bl_g, DDIM, tile_n, k0, tid);
        CP_COMMIT();
    };

    float acc[2][8][4] = {};
    issue(0, 0);
    for (int ks = 0; ks < 16; ks++) {
        if (ks < 15) { issue((ks + 1) & 1, (ks + 1) * 32); CP_WAIT(1); }
        else CP_WAIT(0);
        __syncthreads();
        char* st = dyn + (ks & 1) * 40960;
        mma_hl<2, 8, 40, 40>((const __nv_bfloat16(*)[40])st,
                             (const __nv_bfloat16(*)[40])(st + 10240),
                             (const __nv_bfloat16(*)[40])(st + 20480),
                             (const __nv_bfloat16(*)[40])(st + 30720),
                             wrow, wcol, lane, 0, 0, acc);
        __syncthreads();
    }

    const int r0 = tile_m + wrow + (lane >> 2);
    const int c0 = tile_n + wcol + (lane & 3) * 2;
    #pragma unroll
    for (int mf = 0; mf < 2; mf++)
        #pragma unroll
        for (int hf = 0; hf < 2; hf++) {
            int m = r0 + mf * 16 + hf * 8;
            int b = m >> 11, t = m & (TT - 1);
            #pragma unroll
            for (int nf = 0; nf < 8; nf++) {
                int n = c0 + nf * 8;
                float v0 = acc[mf][nf][hf * 2]     + bias[n];
                float v1 = acc[mf][nf][hf * 2 + 1] + bias[n + 1];
                if (dst == 3) {
                    *(float2*)&outf[(size_t)m * DDIM + n] = make_float2(v0, v1);
                } else {
                    int hh = n >> 6, dk = n & 63;
                    __nv_bfloat16 h0, l0, h1, l1;
                    split_hl(v0, h0, l0);
                    split_hl(v1, h1, l1);
                    if (dst == 2) {
                        size_t base = ((size_t)(b * HH + hh) * DKH + dk) * TT + t;
                        g_vth[base] = h0; g_vtl[base] = l0;
                        g_vth[base + TT] = h1; g_vtl[base + TT] = l1;
                    } else {
                        __nv_bfloat16* dh = (dst == 0) ? g_qh : g_kh;
                        __nv_bfloat16* dl = (dst == 0) ? g_ql : g_kl;
                        size_t idx = ((size_t)(b * HH + hh) * TT + t) * DKH + dk;
                        *(u32*)&dh[idx] = pack2(h0, h1);
                        *(u32*)&dl[idx] = pack2(l0, l1);
                    }
                }
            }
        }
}

// ---------------- fused attention ----------------
// S=QK^T/8 -> exp/mask -> p(unnorm)->aw ; ctx=(p@v)/sum -> g_c hi/lo ;
// tail rescales own aw rows by 1/sum. grid (16 tile_m, 32 bh), 256 thr.
// dyn smem layout (bytes):
//   Qh @0 (18432), Ql @18432 | stage s @36864+s*19456: Kh(4608) Kl Vh(5120) Vl
//   Ph @75776 (10240), Pl @86016 | sInv @96256 (512)  -> total 96768
__global__ __launch_bounds__(256, 2) void fused_attn(float* __restrict__ aw)
{
    extern __shared__ char dyn[];
    __nv_bfloat16 (*sQh)[72] = (__nv_bfloat16(*)[72])(dyn);
    __nv_bfloat16 (*sQl)[72] = (__nv_bfloat16(*)[72])(dyn + 18432);
    __nv_bfloat16 (*sPh)[40] = (__nv_bfloat16(*)[40])(dyn + 75776);
    __nv_bfloat16 (*sPl)[40] = (__nv_bfloat16(*)[40])(dyn + 86016);
    float* sInv = (float*)(dyn + 96256);

    const int tid = threadIdx.x, lane = tid & 31, wid = tid >> 5;
    const int wrow = wid * 16;
    const int tile_m = blockIdx.x * 128;
    const int bz = blockIdx.y;
    const int b = bz >> 3, hh = bz & 7;
    const __nv_bfloat16* qh = g_qh + (size_t)bz * TT * DKH;
    const __nv_bfloat16* ql = g_ql + (size_t)bz * TT * DKH;
    const __nv_bfloat16* kh = g_kh + (size_t)bz * TT * DKH;
    const __nv_bfloat16* kl = g_kl + (size_t)bz * TT * DKH;
    const __nv_bfloat16* vth = g_vth + (size_t)bz * DKH * TT;
    const __nv_bfloat16* vtl = g_vtl + (size_t)bz * DKH * TT;
    const u32 sb = smem_u32(dyn);

    auto issueKV = [&](int s, int kt) {
        u32 base = sb + 36864 + s * 19456;
        cp_tile<32, 64>(base,         kh,  DKH, (size_t)kt * 32, 0, tid);
        cp_tile<32, 64>(base + 4608,  kl,  DKH, (size_t)kt * 32, 0, tid);
        cp_tile<64, 32>(base + 9216,  vth, TT, 0, (size_t)kt * 32, tid);
        cp_tile<64, 32>(base + 14336, vtl, TT, 0, (size_t)kt * 32, tid);
    };

    // preload Q + stage 0 (one commit group)
    cp_tile<128, 64>(sb,         qh, DKH, tile_m, 0, tid);
    cp_tile<128, 64>(sb + 18432, ql, DKH, tile_m, 0, tid);
    issueKV(0, 0);
    CP_COMMIT();

    float acc_av[1][8][4] = {};
    float rs[2] = {0.0f, 0.0f};
    const int rq = (lane >> 2);
    const int cq = (lane & 3) * 2;

    for (int kt = 0; kt < 64; kt++) {
        if (kt < 63) { issueKV((kt + 1) & 1, kt + 1); CP_COMMIT(); CP_WAIT(1); }
        else CP_WAIT(0);
        __syncthreads();

        char* st = dyn + 36864 + (kt & 1) * 19456;
        const __nv_bfloat16 (*sKh)[72] = (const __nv_bfloat16(*)[72])st;
        const __nv_bfloat16 (*sKl)[72] = (const __nv_bfloat16(*)[72])(st + 4608);
        const __nv_bfloat16 (*sVh)[40] = (const __nv_bfloat16(*)[40])(st + 9216);
        const __nv_bfloat16 (*sVl)[40] = (const __nv_bfloat16(*)[40])(st + 14336);

        float acc_s[1][4][4] = {};
        mma_hl<1, 4, 72, 72>(sQh, sQl, sKh, sKl, wrow, 0, lane, 0, 0, acc_s);
        mma_hl<1, 4, 72, 72>(sQh, sQl, sKh, sKl, wrow, 0, lane, 32, 32, acc_s);

        // epilogue: exp + mask, write unnormalized p, accumulate row sums
        #pragma unroll
        for (int hf = 0; hf < 2; hf++) {
            int tq = tile_m + wrow + rq + hf * 8;
            const u32* mrow = g_mbits + ((size_t)b * TT + tq) * (TT / 32);
            float* prow = aw + ((size_t)bz * TT + tq) * TT;
            #pragma unroll
            for (int nf = 0; nf < 4; nf++) {
                int tk = kt * 32 + cq + nf * 8;
                u32 w = mrow[tk >> 5];
                int sh = tk & 31;
                float e0 = acc_s[0][nf][hf * 2]     * 0.125f;
                float e1 = acc_s[0][nf][hf * 2 + 1] * 0.125f;
                float p0 = ((w >> sh) & 1u)       ? __expf(e0) : 0.0f;
                float p1 = ((w >> (sh + 1)) & 1u) ? __expf(e1) : 0.0f;
                rs[hf] += p0 + p1;
                *(float2*)&prow[tk] = make_float2(p0, p1);
                acc_s[0][nf][hf * 2]     = p0;
                acc_s[0][nf][hf * 2 + 1] = p1;
            }
        }

        // stage p hi/lo to smem, then AV accumulate
        #pragma unroll
        for (int hf = 0; hf < 2; hf++) {
            int r = wrow + rq + hf * 8;
            #pragma unroll
            for (int nf = 0; nf < 4; nf++) {
                __nv_bfloat16 h0, l0, h1, l1;
                split_hl(acc_s[0][nf][hf * 2], h0, l0);
                split_hl(acc_s[0][nf][hf * 2 + 1], h1, l1);
                int lc = cq + nf * 8;
                *(u32*)&sPh[r][lc] = pack2(h0, h1);
                *(u32*)&sPl[r][lc] = pack2(l0, l1);
            }
        }
        __syncthreads();
        mma_hl<1, 8, 40, 40>(sPh, sPl, sVh, sVl, wrow, 0, lane, 0, 0, acc_av);
        __syncthreads();
    }

    // deterministic row-sum reduction across the 4 lanes sharing each row
    #pragma unroll
    for (int hf = 0; hf < 2; hf++) {
        rs[hf] += __shfl_xor_sync(0xffffffffu, rs[hf], 1);
        rs[hf] += __shfl_xor_sync(0xffffffffu, rs[hf], 2);
    }
    float inv0 = 1.0f / rs[0], inv1 = 1.0f / rs[1];
    if ((lane & 3) == 0) {
        sInv[wrow + rq]     = inv0;
        sInv[wrow + rq + 8] = inv1;
    }

    // write normalized ctx hi/lo
    #pragma unroll
    for (int hf = 0; hf < 2; hf++) {
        float inv = hf ? inv1 : inv0;
        int tq = tile_m + wrow + rq + hf * 8;
        size_t rowbase = ((size_t)b * TT + tq) * DDIM + hh * DKH;
        #pragma unroll
        for (int nf = 0; nf < 8; nf++) {
            int dk = cq + nf * 8;
            __nv_bfloat16 h0, l0, h1, l1;
            split_hl(acc_av[0][nf][hf * 2] * inv, h0, l0);
            split_hl(acc_av[0][nf][hf * 2 + 1] * inv, h1, l1);
            *(u32*)&g_ch[rowbase + dk] = pack2(h0, h1);
            *(u32*)&g_cl[rowbase + dk] = pack2(l0, l1);
        }
    }
    __syncthreads();

    // tail: rescale own aw rows in place
    const size_t awbase = ((size_t)bz * TT + tile_m) * TT;
    for (int i = tid; i < 128 * 512; i += 256) {
        int r = i >> 9, c = i & 511;
        float inv = sInv[r];
        float4* p4 = (float4*)(aw + awbase + (size_t)r * TT) + c;
        float4 v = *p4;
        v.x *= inv; v.y *= inv; v.z *= inv; v.w *= inv;
        *p4 = v;
    }
}

// -----------------------------------------------------------------------------
extern "C" void kernel_launch(void* const* d_in, const int* in_sizes, int n_in,
                              void* d_out, int out_size)
{
    const float* key   = (const float*)d_in[0];
    const float* value = (const float*)d_in[1];
    const float* query = (const float*)d_in[2];
    const int*   mask  = (const int*)d_in[3];
    const float* Wk = (const float*)d_in[4];
    const float* bk = (const float*)d_in[5];
    const float* Wv = (const float*)d_in[6];
    const float* bv = (const float*)d_in[7];
    const float* Wq = (const float*)d_in[8];
    const float* bq = (const float*)d_in[9];
    const float* Wo = (const float*)d_in[10];
    const float* bo = (const float*)d_in[11];

    float* out = (float*)d_out;
    float* ctx_out = out;                            // [B, T, D]
    float* aw_out  = out + (size_t)BB * TT * DDIM;   // [B, H, T, T]

    // conversions (hi/lo bf16 split) — selectors resolved device-side
    cvt_x<<<SZX / 1024, 256>>>((const float4*)query, 0);
    cvt_x<<<SZX / 1024, 256>>>((const float4*)key,   1);
    cvt_x<<<SZX / 1024, 256>>>((const float4*)value, 2);
    cvt_w<<<SZW / 1024, 256>>>((const float4*)Wq, 0);
    cvt_w<<<SZW / 1024, 256>>>((const float4*)Wk, 1);
    cvt_w<<<SZW / 1024, 256>>>((const float4*)Wv, 2);
    cvt_w<<<SZW / 1024, 256>>>((const float4*)Wo, 3);
    cvt_mask_kernel<<<((size_t)BB * TT * TT) / 256, 256>>>(mask);

    const int GEMM_SMEM = 81920;
    cudaFuncSetAttribute(gemm512, cudaFuncAttributeMaxDynamicSharedMemorySize, GEMM_SMEM);
    dim3 gp(DDIM / 128, (BB * TT) / 128);
    gemm512<<<gp, 256, GEMM_SMEM>>>(0, 0, bq, 0, nullptr);
    gemm512<<<gp, 256, GEMM_SMEM>>>(1, 1, bk, 1, nullptr);
    gemm512<<<gp, 256, GEMM_SMEM>>>(2, 2, bv, 2, nullptr);

    const int FUSED_SMEM = 96768;
    cudaFuncSetAttribute(fused_attn, cudaFuncAttributeMaxDynamicSharedMemorySize, FUSED_SMEM);
    fused_attn<<<dim3(TT / 128, BB * HH), 256, FUSED_SMEM>>>(aw_out);

    gemm512<<<gp, 256, GEMM_SMEM>>>(3, 3, bo, 3, ctx_out);
}

// round 8
// speedup vs baseline: 1.0518x; 1.0518x over previous
#include <cuda_runtime.h>
#include <cuda_bf16.h>
#include <cstdint>

typedef unsigned int u32;

#define BB 4
#define TT 2048
#define DDIM 512
#define HH 8
#define DKH 64

#define SZQ ((size_t)BB * HH * TT * DKH)   // 4,194,304
#define SZX ((size_t)BB * TT * DDIM)       // 4,194,304

// ---------------- scratch (__device__ globals; no allocation) ----------------
__device__ float g_q[SZQ];                        // [B,H,T,DK] fp32
__device__ float g_k[SZQ];                        // [B,H,T,DK] fp32
__device__ float g_vt[SZQ];                       // [B,H,DK,T] fp32 (transposed)
__device__ float g_ctx[SZX];                      // [B,T,D] fp32
__device__ u32 g_mbits[(size_t)BB * TT * (TT / 32)];  // packed mask bits

// ---------------- helpers ----------------
__device__ __forceinline__ u32 smem_u32(const void* p) {
    u32 a;
    asm("{ .reg .u64 t; cvta.to.shared.u64 t, %1; cvt.u32.u64 %0, t; }" : "=r"(a) : "l"(p));
    return a;
}
__device__ __forceinline__ void split_hl(float v, __nv_bfloat16& h, __nv_bfloat16& l) {
    h = __float2bfloat16(v);
    l = __float2bfloat16(v - __bfloat162float(h));
}
__device__ __forceinline__ u32 pack2(__nv_bfloat16 a, __nv_bfloat16 b) {
    return (u32)__bfloat16_as_ushort(a) | ((u32)__bfloat16_as_ushort(b) << 16);
}
__device__ __forceinline__ void ldsm_x4(u32& r0, u32& r1, u32& r2, u32& r3, u32 addr) {
    asm volatile("ldmatrix.sync.aligned.m8n8.x4.shared.b16 {%0,%1,%2,%3}, [%4];"
                 : "=r"(r0), "=r"(r1), "=r"(r2), "=r"(r3) : "r"(addr));
}
__device__ __forceinline__ void mma16816(float* c, const u32* a, u32 b0, u32 b1) {
    asm volatile(
        "mma.sync.aligned.m16n8k16.row.col.f32.bf16.bf16.f32 "
        "{%0,%1,%2,%3}, {%4,%5,%6,%7}, {%8,%9}, {%0,%1,%2,%3};"
        : "+f"(c[0]), "+f"(c[1]), "+f"(c[2]), "+f"(c[3])
        : "r"(a[0]), "r"(a[1]), "r"(a[2]), "r"(a[3]), "r"(b0), "r"(b1));
}

// fp32 source [rows][ld] -> bf16 hi/lo smem tiles. W4 float4-groups per row.
template <int ROWS, int W4, int STRIDE>
__device__ __forceinline__ void load_f32_hl(
    __nv_bfloat16 (*sh)[STRIDE], __nv_bfloat16 (*sl)[STRIDE],
    const float* __restrict__ g, size_t ld, size_t row0, int k0, int tid)
{
    #pragma unroll
    for (int i = tid; i < ROWS * W4; i += 256) {
        int r = i / W4, c = i % W4;
        float4 v = *(const float4*)&g[(row0 + (size_t)r) * ld + k0 + c * 4];
        __nv_bfloat16 h0, l0, h1, l1, h2, l2, h3, l3;
        split_hl(v.x, h0, l0); split_hl(v.y, h1, l1);
        split_hl(v.z, h2, l2); split_hl(v.w, h3, l3);
        *(uint2*)&sh[r][c * 4] = make_uint2(pack2(h0, h1), pack2(h2, h3));
        *(uint2*)&sl[r][c * 4] = make_uint2(pack2(l0, l1), pack2(l2, l3));
    }
}

// warp-MMA over one 32-wide K slab, bf16x3 emulation (3 MMA terms)
template <int MF, int NF, int AS, int BS>
__device__ __forceinline__ void mma_hl(
    const __nv_bfloat16 (*Ah)[AS], const __nv_bfloat16 (*Al)[AS],
    const __nv_bfloat16 (*Bh)[BS], const __nv_bfloat16 (*Bl)[BS],
    int wrow, int wcol, int lane, int kA, int kB, float acc[MF][NF][4])
{
    const int arow = wrow + (lane & 15);
    const int akh = (lane >> 4) << 3;
    const int brow = wcol + (lane & 7) + ((lane & 16) >> 1);
    const int bkh = (lane & 8);
    #pragma unroll
    for (int ks = 0; ks < 32; ks += 16) {
        u32 ah[MF][4], al[MF][4];
        #pragma unroll
        for (int mf = 0; mf < MF; mf++) {
            ldsm_x4(ah[mf][0], ah[mf][1], ah[mf][2], ah[mf][3],
                    smem_u32(&Ah[arow + mf * 16][kA + ks + akh]));
            ldsm_x4(al[mf][0], al[mf][1], al[mf][2], al[mf][3],
                    smem_u32(&Al[arow + mf * 16][kA + ks + akh]));
        }
        #pragma unroll
        for (int np = 0; np < NF / 2; np++) {
            u32 bh0, bh1, bh2, bh3, bl0, bl1, bl2, bl3;
            ldsm_x4(bh0, bh1, bh2, bh3, smem_u32(&Bh[brow + np * 16][kB + ks + bkh]));
            ldsm_x4(bl0, bl1, bl2, bl3, smem_u32(&Bl[brow + np * 16][kB + ks + bkh]));
            #pragma unroll
            for (int mf = 0; mf < MF; mf++) {
                mma16816(acc[mf][2 * np],     ah[mf], bh0, bh1);
                mma16816(acc[mf][2 * np],     ah[mf], bl0, bl1);
                mma16816(acc[mf][2 * np],     al[mf], bh0, bh1);
                mma16816(acc[mf][2 * np + 1], ah[mf], bh2, bh3);
                mma16816(acc[mf][2 * np + 1], ah[mf], bl2, bl3);
                mma16816(acc[mf][2 * np + 1], al[mf], bh2, bh3);
            }
        }
    }
}

// ---------------- mask bit packing ----------------
__global__ __launch_bounds__(256) void cvt_mask_kernel(const int* __restrict__ mask)
{
    size_t i = (size_t)blockIdx.x * 256 + threadIdx.x;
    u32 bit = (mask[i] != 0) ? 1u : 0u;
    u32 word = __ballot_sync(0xffffffffu, bit);
    if ((threadIdx.x & 31) == 0) g_mbits[i >> 5] = word;
}

// ---------------- proj: out = X @ W^T + b -> q/k fp32 [B,H,T,DK], vt [B,H,DK,T]
__global__ __launch_bounds__(256, 2) void proj_mma(const float* __restrict__ X,
                                                   const float* __restrict__ W,
                                                   const float* __restrict__ bias, int dst)
{
    __shared__ __nv_bfloat16 sAh[128][40], sAl[128][40];
    __shared__ __nv_bfloat16 sBh[128][40], sBl[128][40];
    const int tid = threadIdx.x, lane = tid & 31, wid = tid >> 5;
    const int wrow = (wid >> 1) * 32, wcol = (wid & 1) * 64;
    const int tile_m = blockIdx.y * 128, tile_n = blockIdx.x * 128;

    float acc[2][8][4] = {};
    for (int k0 = 0; k0 < DDIM; k0 += 32) {
        __syncthreads();
        load_f32_hl<128, 8, 40>(sAh, sAl, X, DDIM, tile_m, k0, tid);
        load_f32_hl<128, 8, 40>(sBh, sBl, W, DDIM, tile_n, k0, tid);
        __syncthreads();
        mma_hl<2, 8, 40, 40>(sAh, sAl, sBh, sBl, wrow, wcol, lane, 0, 0, acc);
    }

    float* dq = (dst == 0) ? g_q : g_k;
    const int r0 = tile_m + wrow + (lane >> 2);
    const int c0 = tile_n + wcol + (lane & 3) * 2;
    #pragma unroll
    for (int mf = 0; mf < 2; mf++)
        #pragma unroll
        for (int hf = 0; hf < 2; hf++) {
            int m = r0 + mf * 16 + hf * 8;
            int b = m >> 11, t = m & (TT - 1);
            #pragma unroll
            for (int nf = 0; nf < 8; nf++) {
                int n = c0 + nf * 8;
                float v0 = acc[mf][nf][hf * 2]     + bias[n];
                float v1 = acc[mf][nf][hf * 2 + 1] + bias[n + 1];
                int hh = n >> 6, dk = n & 63;
                if (dst == 2) {
                    size_t base = ((size_t)(b * HH + hh) * DKH + dk) * TT + t;
                    g_vt[base] = v0;
                    g_vt[base + TT] = v1;
                } else {
                    size_t idx = ((size_t)(b * HH + hh) * TT + t) * DKH + dk;
                    *(float2*)&dq[idx] = make_float2(v0, v1);
                }
            }
        }
}

// ---------------- fused 2-pass attention ----------------
// Pass A: sweep K tiles, S=QK^T/8 -> exp/mask -> row sums (no stores).
// Pass B: recompute S, write NORMALIZED p to aw, accumulate ctx = p_norm @ v.
// grid (16 tile_m, 32 bh), 256 thr, dynamic smem 94208 B.
__global__ __launch_bounds__(256, 2) void fused_attn(float* __restrict__ aw)
{
    extern __shared__ __nv_bfloat16 dyn[];
    __nv_bfloat16 (*sQh)[72] = (__nv_bfloat16 (*)[72])(dyn);
    __nv_bfloat16 (*sQl)[72] = (__nv_bfloat16 (*)[72])(dyn + 9216);
    __nv_bfloat16 (*sKh)[72] = (__nv_bfloat16 (*)[72])(dyn + 18432);
    __nv_bfloat16 (*sKl)[72] = (__nv_bfloat16 (*)[72])(dyn + 23040);
    __nv_bfloat16 (*sVh)[72] = (__nv_bfloat16 (*)[72])(dyn + 27648);
    __nv_bfloat16 (*sVl)[72] = (__nv_bfloat16 (*)[72])(dyn + 32256);
    __nv_bfloat16 (*sPh)[40] = (__nv_bfloat16 (*)[40])(dyn + 36864);
    __nv_bfloat16 (*sPl)[40] = (__nv_bfloat16 (*)[40])(dyn + 41984);

    const int tid = threadIdx.x, lane = tid & 31, wid = tid >> 5;
    const int wrow = wid * 16;
    const int tile_m = blockIdx.x * 128;
    const int bz = blockIdx.y;
    const int b = bz >> 3, hh = bz & 7;
    const float* qp = g_q + (size_t)bz * TT * DKH;
    const float* kp = g_k + (size_t)bz * TT * DKH;
    const float* vt = g_vt + (size_t)bz * DKH * TT;

    load_f32_hl<128, 16, 72>(sQh, sQl, qp, DKH, tile_m, 0, tid);

    const int rq = (lane >> 2);
    const int cq = (lane & 3) * 2;

    // ---------------- pass A: row sums only ----------------
    float rs[2] = {0.0f, 0.0f};
    for (int kt = 0; kt < 32; kt++) {
        __syncthreads();
        load_f32_hl<64, 16, 72>(sKh, sKl, kp, DKH, kt * 64, 0, tid);
        __syncthreads();

        float acc_s[1][8][4] = {};
        mma_hl<1, 8, 72, 72>(sQh, sQl, sKh, sKl, wrow, 0, lane, 0, 0, acc_s);
        mma_hl<1, 8, 72, 72>(sQh, sQl, sKh, sKl, wrow, 0, lane, 32, 32, acc_s);

        #pragma unroll
        for (int hf = 0; hf < 2; hf++) {
            int tq = tile_m + wrow + rq + hf * 8;
            const u32* mrow = g_mbits + ((size_t)b * TT + tq) * (TT / 32);
            #pragma unroll
            for (int nf = 0; nf < 8; nf++) {
                int tk = kt * 64 + cq + nf * 8;
                u32 w = mrow[tk >> 5];
                int sh = tk & 31;
                float e0 = acc_s[0][nf][hf * 2]     * 0.125f;
                float e1 = acc_s[0][nf][hf * 2 + 1] * 0.125f;
                if ((w >> sh) & 1u)       rs[hf] += __expf(e0);
                if ((w >> (sh + 1)) & 1u) rs[hf] += __expf(e1);
            }
        }
    }
    // deterministic reduction across the 4 lanes sharing each row
    #pragma unroll
    for (int hf = 0; hf < 2; hf++) {
        rs[hf] += __shfl_xor_sync(0xffffffffu, rs[hf], 1);
        rs[hf] += __shfl_xor_sync(0xffffffffu, rs[hf], 2);
    }
    const float inv0 = 1.0f / rs[0], inv1 = 1.0f / rs[1];

    // ---------------- pass B: normalized p -> aw, ctx = p_norm @ v ----------
    float acc_av[1][8][4] = {};
    for (int kt = 0; kt < 32; kt++) {
        __syncthreads();
        load_f32_hl<64, 16, 72>(sKh, sKl, kp, DKH, kt * 64, 0, tid);
        load_f32_hl<64, 16, 72>(sVh, sVl, vt, TT, 0, kt * 64, tid);
        __syncthreads();

        float acc_s[1][8][4] = {};
        mma_hl<1, 8, 72, 72>(sQh, sQl, sKh, sKl, wrow, 0, lane, 0, 0, acc_s);
        mma_hl<1, 8, 72, 72>(sQh, sQl, sKh, sKl, wrow, 0, lane, 32, 32, acc_s);

        #pragma unroll
        for (int hf = 0; hf < 2; hf++) {
            float inv = hf ? inv1 : inv0;
            int tq = tile_m + wrow + rq + hf * 8;
            const u32* mrow = g_mbits + ((size_t)b * TT + tq) * (TT / 32);
            float* prow = aw + ((size_t)bz * TT + tq) * TT;
            #pragma unroll
            for (int nf = 0; nf < 8; nf++) {
                int tk = kt * 64 + cq + nf * 8;
                u32 w = mrow[tk >> 5];
                int sh = tk & 31;
                float e0 = acc_s[0][nf][hf * 2]     * 0.125f;
                float e1 = acc_s[0][nf][hf * 2 + 1] * 0.125f;
                float p0 = ((w >> sh) & 1u)       ? __expf(e0) * inv : 0.0f;
                float p1 = ((w >> (sh + 1)) & 1u) ? __expf(e1) * inv : 0.0f;
                *(float2*)&prow[tk] = make_float2(p0, p1);
                acc_s[0][nf][hf * 2]     = p0;
                acc_s[0][nf][hf * 2 + 1] = p1;
            }
        }

        // stage normalized p hi/lo to smem, AV accumulate (two 32-wide slabs)
        #pragma unroll
        for (int cb = 0; cb < 2; cb++) {
            __syncthreads();
            #pragma unroll
            for (int hf = 0; hf < 2; hf++) {
                int r = wrow + rq + hf * 8;
                #pragma unroll
                for (int nf4 = 0; nf4 < 4; nf4++) {
                    int nf = cb * 4 + nf4;
                    __nv_bfloat16 h0, l0, h1, l1;
                    split_hl(acc_s[0][nf][hf * 2], h0, l0);
                    split_hl(acc_s[0][nf][hf * 2 + 1], h1, l1);
                    int lc = cq + nf4 * 8;
                    *(u32*)&sPh[r][lc] = pack2(h0, h1);
                    *(u32*)&sPl[r][lc] = pack2(l0, l1);
                }
            }
            __syncthreads();
            mma_hl<1, 8, 40, 72>(sPh, sPl, sVh, sVl, wrow, 0, lane, 0, cb * 32, acc_av);
        }
    }

    // write ctx (already normalized)
    #pragma unroll
    for (int hf = 0; hf < 2; hf++) {
        int tq = tile_m + wrow + rq + hf * 8;
        float* crow = g_ctx + ((size_t)b * TT + tq) * DDIM + hh * DKH;
        #pragma unroll
        for (int nf = 0; nf < 8; nf++) {
            int dk = cq + nf * 8;
            *(float2*)&crow[dk] = make_float2(acc_av[0][nf][hf * 2],
                                              acc_av[0][nf][hf * 2 + 1]);
        }
    }
}

// ---------------- outproj: out = ctx @ Wo^T + bo -> fp32 d_out --------------
__global__ __launch_bounds__(256, 2) void outproj_mma(const float* __restrict__ Wo,
                                                      const float* __restrict__ bo,
                                                      float* __restrict__ out)
{
    __shared__ __nv_bfloat16 sAh[128][40], sAl[128][40];
    __shared__ __nv_bfloat16 sBh[128][40], sBl[128][40];
    const int tid = threadIdx.x, lane = tid & 31, wid = tid >> 5;
    const int wrow = (wid >> 1) * 32, wcol = (wid & 1) * 64;
    const int tile_m = blockIdx.y * 128, tile_n = blockIdx.x * 128;

    float acc[2][8][4] = {};
    for (int k0 = 0; k0 < DDIM; k0 += 32) {
        __syncthreads();
        load_f32_hl<128, 8, 40>(sAh, sAl, g_ctx, DDIM, tile_m, k0, tid);
        load_f32_hl<128, 8, 40>(sBh, sBl, Wo, DDIM, tile_n, k0, tid);
        __syncthreads();
        mma_hl<2, 8, 40, 40>(sAh, sAl, sBh, sBl, wrow, wcol, lane, 0, 0, acc);
    }

    const int r0 = tile_m + wrow + (lane >> 2);
    const int c0 = tile_n + wcol + (lane & 3) * 2;
    #pragma unroll
    for (int mf = 0; mf < 2; mf++)
        #pragma unroll
        for (int hf = 0; hf < 2; hf++) {
            int m = r0 + mf * 16 + hf * 8;
            #pragma unroll
            for (int nf = 0; nf < 8; nf++) {
                int n = c0 + nf * 8;
                *(float2*)&out[(size_t)m * DDIM + n] =
                    make_float2(acc[mf][nf][hf * 2] + bo[n],
                                acc[mf][nf][hf * 2 + 1] + bo[n + 1]);
            }
        }
}

// -----------------------------------------------------------------------------
extern "C" void kernel_launch(void* const* d_in, const int* in_sizes, int n_in,
                              void* d_out, int out_size)
{
    const float* key   = (const float*)d_in[0];
    const float* value = (const float*)d_in[1];
    const float* query = (const float*)d_in[2];
    const int*   mask  = (const int*)d_in[3];
    const float* Wk = (const float*)d_in[4];
    const float* bk = (const float*)d_in[5];
    const float* Wv = (const float*)d_in[6];
    const float* bv = (const float*)d_in[7];
    const float* Wq = (const float*)d_in[8];
    const float* bq = (const float*)d_in[9];
    const float* Wo = (const float*)d_in[10];
    const float* bo = (const float*)d_in[11];

    float* out = (float*)d_out;
    float* ctx_out = out;                            // [B, T, D]
    float* aw_out  = out + (size_t)BB * TT * DDIM;   // [B, H, T, T]

    cvt_mask_kernel<<<((size_t)BB * TT * TT) / 256, 256>>>(mask);

    dim3 gp(DDIM / 128, (BB * TT) / 128);
    proj_mma<<<gp, 256>>>(query, Wq, bq, 0);
    proj_mma<<<gp, 256>>>(key,   Wk, bk, 1);
    proj_mma<<<gp, 256>>>(value, Wv, bv, 2);

    // fused 2-pass attention: dynamic smem 94,208 B
    const int FUSED_SMEM = 94208;
    cudaFuncSetAttribute(fused_attn, cudaFuncAttributeMaxDynamicSharedMemorySize,
                         FUSED_SMEM);
    fused_attn<<<dim3(TT / 128, BB * HH), 256, FUSED_SMEM>>>(aw_out);

    outproj_mma<<<gp, 256>>>(Wo, bo, ctx_out);
}